// round 3
// baseline (speedup 1.0000x reference)
#include <cuda_runtime.h>

#define NB 8192
#define NK 16
#define ND 512
#define NS 4

// ---------------- scratch (device globals: allocation-free) ----------------
__device__ float buf_ctx [(size_t)NB * ND];
__device__ float buf_mkf [(size_t)NB * NK];
__device__ float buf_h1  [(size_t)NB * 2 * ND];
__device__ float buf_ws  [(size_t)NB * NS * ND];
__device__ float buf_qw  [(size_t)NB * NS * ND];
__device__ float buf_kw  [(size_t)NB * NK * ND];
__device__ float buf_vw  [(size_t)NB * NK * ND];
__device__ float buf_wsu [(size_t)NB * NS * ND];
__device__ float buf_qr  [(size_t)NB * NK * ND];
__device__ float buf_kr  [(size_t)NB * NS * ND];
__device__ float buf_vr  [(size_t)NB * NS * ND];
__device__ float buf_bc0 [(size_t)NB * NK * ND];
__device__ float buf_bc  [(size_t)NB * NK * ND];

__device__ __forceinline__ float warp_sum(float v) {
    #pragma unroll
    for (int o = 16; o > 0; o >>= 1) v += __shfl_xor_sync(0xffffffffu, v, o);
    return v;
}

__device__ __forceinline__ float f2tf32(float f) {
    unsigned r;
    asm("cvt.rna.tf32.f32 %0, %1;" : "=r"(r) : "f"(f));
    return __uint_as_float(r);
}

__device__ __forceinline__ void mma_tf32(float c[4], const unsigned a[4], const unsigned b[2]) {
    asm volatile(
        "mma.sync.aligned.m16n8k8.row.col.f32.tf32.tf32.f32 "
        "{%0,%1,%2,%3}, {%4,%5,%6,%7}, {%8,%9}, {%0,%1,%2,%3};"
        : "+f"(c[0]), "+f"(c[1]), "+f"(c[2]), "+f"(c[3])
        : "r"(a[0]), "r"(a[1]), "r"(a[2]), "r"(a[3]), "r"(b[0]), "r"(b[1]));
}

// ---------------- kernel 1: masked context pooling + mask normalize --------
__global__ void ctx_kernel(const float* __restrict__ hidden, const void* mask_raw) {
    int b = blockIdx.x;
    int tid = threadIdx.x;
    __shared__ float sm[NK];
    __shared__ int smode;
    if (tid == 0) {
        const unsigned char* p = (const unsigned char*)mask_raw;
        int mode = 0;
        for (int i = 0; i < 512; ++i) {
            unsigned char v = p[i];
            if (!v) continue;
            if (v != 1u) { mode = 2; break; }
            if (i & 3)   { mode = 1; break; }
        }
        smode = mode;
    }
    __syncthreads();
    int mode = smode;
    if (tid < NK) {
        int idx = b * NK + tid;
        float m;
        if (mode == 1)      m = ((const unsigned char*)mask_raw)[idx] ? 1.f : 0.f;
        else if (mode == 0) m = ((const int*)mask_raw)[idx] ? 1.f : 0.f;
        else                m = ((const float*)mask_raw)[idx];
        sm[tid] = m;
        buf_mkf[idx] = m;
    }
    __syncthreads();
    float n = 0.f;
    #pragma unroll
    for (int k = 0; k < NK; ++k) n += sm[k];
    n = fmaxf(n, 1.f);
    float acc = 0.f;
    #pragma unroll
    for (int k = 0; k < NK; ++k)
        acc += sm[k] * hidden[((size_t)b * NK + k) * ND + tid];
    buf_ctx[(size_t)b * ND + tid] = acc / n;
}

// ---------------- TF32 tensor-core SGEMM, fragment-major smem --------------
// 128x128 CTA tile, BK=16, 256 threads = 8 warps (2x4), 64x32 warp tile.
// Smem holds tiles in MMA fragment order: A frag = 16B/lane (LDS.128),
// B frag = 8B/lane (LDS.64). Fill: each warp gathers+stores its fragments.
#define AOFF(kb, rb, lane) ((((kb)*8  + (rb))*32 + (lane))*4)
#define BOFF(kb, nb, lane) ((((kb)*16 + (nb))*32 + (lane))*2)

__global__ void __launch_bounds__(256, 2)
sgemm_tc(const float* __restrict__ A, const float* __restrict__ B,
         float* __restrict__ C, int M, int N, int K,
         const float* __restrict__ bias1, const float* __restrict__ bias2,
         int do_gelu) {
    __shared__ float As[2][2048];
    __shared__ float Bs[2][2048];

    const int bm = blockIdx.y * 128;
    const int bn = blockIdx.x * 128;
    const int tid  = threadIdx.x;
    const int warp = tid >> 5;
    const int lane = tid & 31;
    const int gid  = lane >> 2;
    const int tig  = lane & 3;
    const int wrb  = (warp >> 2) * 4;    // warp's first A row-block (16-row units)
    const int wnb  = (warp & 3) * 4;     // warp's first B col-block (8-col units)

    // fill ownership: warp w loads A row-block rb=w, B col-blocks nb=2w,2w+1
    const float* Ag0 = A + (size_t)(bm + warp * 16 + gid) * K + tig;
    const float* Ag1 = Ag0 + (size_t)8 * K;
    const float* Bg0 = B + bn + (warp * 2) * 8 + gid + (size_t)tig * N;
    const float* Bg1 = Bg0 + 8;

    float acc[4][4][4];
    #pragma unroll
    for (int i = 0; i < 4; ++i)
        #pragma unroll
        for (int j = 0; j < 4; ++j)
            #pragma unroll
            for (int r = 0; r < 4; ++r) acc[i][j][r] = 0.f;

    const int nk = K >> 4;
    float pa[2][4];       // prefetched A regs [kb][reg]
    float pb[2][2][2];    // prefetched B regs [nbi][kb][reg]

    auto load_regs = [&](int k0) {
        #pragma unroll
        for (int kb = 0; kb < 2; ++kb) {
            const int c = k0 + kb * 8;
            pa[kb][0] = Ag0[c];     pa[kb][1] = Ag1[c];
            pa[kb][2] = Ag0[c + 4]; pa[kb][3] = Ag1[c + 4];
            #pragma unroll
            for (int nbi = 0; nbi < 2; ++nbi) {
                const float* bp = (nbi ? Bg1 : Bg0) + (size_t)c * N;
                pb[nbi][kb][0] = bp[0];
                pb[nbi][kb][1] = bp[(size_t)4 * N];
            }
        }
    };
    auto store_stage = [&](int st) {
        #pragma unroll
        for (int kb = 0; kb < 2; ++kb) {
            *(float4*)&As[st][AOFF(kb, warp, lane)] =
                make_float4(f2tf32(pa[kb][0]), f2tf32(pa[kb][1]),
                            f2tf32(pa[kb][2]), f2tf32(pa[kb][3]));
            #pragma unroll
            for (int nbi = 0; nbi < 2; ++nbi)
                *(float2*)&Bs[st][BOFF(kb, warp * 2 + nbi, lane)] =
                    make_float2(f2tf32(pb[nbi][kb][0]), f2tf32(pb[nbi][kb][1]));
        }
    };

    load_regs(0);
    store_stage(0);
    __syncthreads();

    for (int kt = 0; kt < nk; ++kt) {
        const int st = kt & 1;
        if (kt + 1 < nk) load_regs((kt + 1) << 4);

        #pragma unroll
        for (int kb = 0; kb < 2; ++kb) {
            unsigned afr[4][4], bfr[4][2];
            #pragma unroll
            for (int i = 0; i < 4; ++i) {
                float4 av = *(const float4*)&As[st][AOFF(kb, wrb + i, lane)];
                afr[i][0] = __float_as_uint(av.x); afr[i][1] = __float_as_uint(av.y);
                afr[i][2] = __float_as_uint(av.z); afr[i][3] = __float_as_uint(av.w);
            }
            #pragma unroll
            for (int j = 0; j < 4; ++j) {
                float2 bv = *(const float2*)&Bs[st][BOFF(kb, wnb + j, lane)];
                bfr[j][0] = __float_as_uint(bv.x); bfr[j][1] = __float_as_uint(bv.y);
            }
            #pragma unroll
            for (int i = 0; i < 4; ++i)
                #pragma unroll
                for (int j = 0; j < 4; ++j)
                    mma_tf32(acc[i][j], afr[i], bfr[j]);
        }
        if (kt + 1 < nk) store_stage((kt + 1) & 1);
        __syncthreads();
    }

    // epilogue (thread owns rows gid/gid+8, cols tig*2, tig*2+1 per 16x8 tile)
    #pragma unroll
    for (int i = 0; i < 4; ++i) {
        #pragma unroll
        for (int j = 0; j < 4; ++j) {
            #pragma unroll
            for (int half = 0; half < 2; ++half) {
                const int row = bm + (wrb + i) * 16 + gid + half * 8;
                const int col = bn + (wnb + j) * 8 + tig * 2;
                float v0 = acc[i][j][half * 2 + 0];
                float v1 = acc[i][j][half * 2 + 1];
                if (bias1) { v0 += bias1[col]; v1 += bias1[col + 1]; }
                if (bias2) { v0 += bias2[col]; v1 += bias2[col + 1]; }
                if (do_gelu) {
                    v0 = 0.5f * v0 * (1.f + erff(v0 * 0.70710678118654752f));
                    v1 = 0.5f * v1 * (1.f + erff(v1 * 0.70710678118654752f));
                }
                *(float2*)(C + (size_t)row * N + col) = make_float2(v0, v1);
            }
        }
    }
}

// ---------------- attention #1 (ws queries hidden) + LN, parallel ----------
// 256 threads/CTA, one CTA per batch.
__global__ void __launch_bounds__(256) attn1_kernel(const float* __restrict__ gamma,
                                                    const float* __restrict__ beta) {
    __shared__ float sq[NS * ND];        // q, then reused for y
    __shared__ float sv[NK * ND];
    __shared__ float slog[NS * NK];
    __shared__ float swt[NS * NK];
    const int b = blockIdx.x;
    const int tid = threadIdx.x;
    const int warp = tid >> 5;
    const int lane = tid & 31;

    // stage Q (2048 floats) and V (8192 floats)
    {
        const float4* qg = (const float4*)(buf_qw + (size_t)b * NS * ND);
        float4* s4 = (float4*)sq;
        #pragma unroll
        for (int i = 0; i < 2; ++i) s4[tid + 256 * i] = qg[tid + 256 * i];
        const float4* vg = (const float4*)(buf_vw + (size_t)b * NK * ND);
        float4* v4 = (float4*)sv;
        #pragma unroll
        for (int i = 0; i < 8; ++i) v4[tid + 256 * i] = vg[tid + 256 * i];
    }
    __syncthreads();

    // logits: 64 (s,k) pairs; warp w owns pairs w*8..w*8+7, 8-way ILP
    {
        float acc[8];
        #pragma unroll
        for (int u = 0; u < 8; ++u) acc[u] = 0.f;
        const int p0 = warp * 8;
        const float* kwb = buf_kw + (size_t)b * NK * ND;
        for (int d = lane; d < ND; d += 32) {
            #pragma unroll
            for (int u = 0; u < 8; ++u) {
                const int p = p0 + u;
                acc[u] = fmaf(sq[(p >> 4) * ND + d], kwb[(p & 15) * ND + d], acc[u]);
            }
        }
        #pragma unroll
        for (int u = 0; u < 8; ++u) acc[u] = warp_sum(acc[u]);
        if (lane == 0) {
            #pragma unroll
            for (int u = 0; u < 8; ++u) slog[p0 + u] = acc[u];
        }
    }
    __syncthreads();

    // softmax per slot s (4 threads)
    if (tid < NS) {
        const int s = tid;
        const float scale = 0.04419417382415922f;
        float lg[NK];
        float mx = -1e30f;
        int any = 0;
        #pragma unroll
        for (int k = 0; k < NK; ++k) {
            float m = buf_mkf[b * NK + k];
            float l = (m > 0.5f) ? slog[s * NK + k] * scale : -1e30f;
            if (m > 0.5f) any = 1;
            lg[k] = l;
            mx = fmaxf(mx, l);
        }
        float den = 0.f;
        #pragma unroll
        for (int k = 0; k < NK; ++k) { lg[k] = expf(lg[k] - mx); den += lg[k]; }
        const float inv = any ? (1.f / den) : 0.f;
        #pragma unroll
        for (int k = 0; k < NK; ++k) swt[s * NK + k] = lg[k] * inv;
    }
    __syncthreads();

    // y = ws + attn @ V  (write into sq; q no longer needed)
    {
        const float* wsb = buf_ws + (size_t)b * NS * ND;
        #pragma unroll
        for (int i = 0; i < 8; ++i) {
            const int e = tid + 256 * i;
            const int s = e >> 9, d = e & 511;
            float o = 0.f;
            #pragma unroll
            for (int k = 0; k < NK; ++k)
                o = fmaf(swt[s * NK + k], sv[k * ND + d], o);
            sq[e] = wsb[e] + o;
        }
    }
    __syncthreads();

    // layernorm per slot (warps 0..3)
    if (warp < NS) {
        const int s = warp;
        float y[16];
        #pragma unroll
        for (int t = 0; t < 16; ++t) y[t] = sq[s * ND + lane + 32 * t];
        float sum = 0.f;
        #pragma unroll
        for (int t = 0; t < 16; ++t) sum += y[t];
        const float mu = warp_sum(sum) * (1.f / ND);
        float sqs = 0.f;
        #pragma unroll
        for (int t = 0; t < 16; ++t) { float c = y[t] - mu; sqs += c * c; }
        const float var = warp_sum(sqs) * (1.f / ND);
        const float rstd = rsqrtf(var + 1e-5f);
        #pragma unroll
        for (int t = 0; t < 16; ++t) {
            const int d = lane + 32 * t;
            buf_wsu[((size_t)b * NS + s) * ND + d] = (y[t] - mu) * rstd * gamma[d] + beta[d];
        }
    }
}

// ---------------- attention #2 (hidden queries ws_upd), parallel -----------
__global__ void __launch_bounds__(256) attn2_kernel() {
    __shared__ float skr[NS * ND];
    __shared__ float svr[NS * ND];
    __shared__ float slog[NK * NS];
    __shared__ float swt[NK * NS];
    const int b = blockIdx.x;
    const int tid = threadIdx.x;
    const int warp = tid >> 5;
    const int lane = tid & 31;

    {
        const float4* kg = (const float4*)(buf_kr + (size_t)b * NS * ND);
        const float4* vg = (const float4*)(buf_vr + (size_t)b * NS * ND);
        float4* k4 = (float4*)skr;
        float4* v4 = (float4*)svr;
        #pragma unroll
        for (int i = 0; i < 2; ++i) {
            k4[tid + 256 * i] = kg[tid + 256 * i];
            v4[tid + 256 * i] = vg[tid + 256 * i];
        }
    }
    __syncthreads();

    // logits: warp w owns tokens k = 2w, 2w+1; 8-way ILP over (k,s)
    {
        float acc[2][4];
        #pragma unroll
        for (int i = 0; i < 2; ++i)
            #pragma unroll
            for (int s = 0; s < 4; ++s) acc[i][s] = 0.f;
        const float* qb = buf_qr + (size_t)b * NK * ND;
        const float* q0 = qb + (size_t)(2 * warp) * ND;
        const float* q1 = q0 + ND;
        for (int d = lane; d < ND; d += 32) {
            const float a0 = q0[d], a1 = q1[d];
            #pragma unroll
            for (int s = 0; s < 4; ++s) {
                const float kv = skr[s * ND + d];
                acc[0][s] = fmaf(a0, kv, acc[0][s]);
                acc[1][s] = fmaf(a1, kv, acc[1][s]);
            }
        }
        #pragma unroll
        for (int i = 0; i < 2; ++i)
            #pragma unroll
            for (int s = 0; s < 4; ++s) acc[i][s] = warp_sum(acc[i][s]);
        if (lane == 0) {
            #pragma unroll
            for (int i = 0; i < 2; ++i)
                #pragma unroll
                for (int s = 0; s < 4; ++s) slog[(2 * warp + i) * NS + s] = acc[i][s];
        }
    }
    __syncthreads();

    if (tid < NK) {
        const int k = tid;
        const float scale = 0.04419417382415922f;
        float lg[NS];
        float mx = -1e30f;
        #pragma unroll
        for (int s = 0; s < NS; ++s) { lg[s] = slog[k * NS + s] * scale; mx = fmaxf(mx, lg[s]); }
        float den = 0.f;
        #pragma unroll
        for (int s = 0; s < NS; ++s) { lg[s] = expf(lg[s] - mx); den += lg[s]; }
        const float inv = 1.f / den;
        #pragma unroll
        for (int s = 0; s < NS; ++s) swt[k * NS + s] = lg[s] * inv;
    }
    __syncthreads();

    {
        float* ob = buf_bc0 + (size_t)b * NK * ND;
        #pragma unroll
        for (int i = 0; i < 32; ++i) {
            const int e = tid + 256 * i;
            const int k = e >> 9, d = e & 511;
            float o = swt[k * NS + 0] * svr[d];
            o = fmaf(swt[k * NS + 1], svr[ND + d], o);
            o = fmaf(swt[k * NS + 2], svr[2 * ND + d], o);
            o = fmaf(swt[k * NS + 3], svr[3 * ND + d], o);
            ob[e] = o;
        }
    }
}

// ---------------- final residual + layernorm --------------------------------
__global__ void lnout_kernel(const float* __restrict__ hidden,
                             const float* __restrict__ gamma,
                             const float* __restrict__ beta,
                             float* __restrict__ out) {
    const int row = blockIdx.x * 8 + (threadIdx.x >> 5);
    const int lane = threadIdx.x & 31;
    float y[16];
    #pragma unroll
    for (int t = 0; t < 16; ++t) {
        int d = lane + 32 * t;
        y[t] = hidden[(size_t)row * ND + d] + buf_bc[(size_t)row * ND + d];
    }
    float sum = 0.f;
    #pragma unroll
    for (int t = 0; t < 16; ++t) sum += y[t];
    const float mu = warp_sum(sum) * (1.f / ND);
    float sq = 0.f;
    #pragma unroll
    for (int t = 0; t < 16; ++t) { float c = y[t] - mu; sq += c * c; }
    const float var = warp_sum(sq) * (1.f / ND);
    const float rstd = rsqrtf(var + 1e-5f);
    #pragma unroll
    for (int t = 0; t < 16; ++t) {
        int d = lane + 32 * t;
        out[(size_t)row * ND + d] = (y[t] - mu) * rstd * gamma[d] + beta[d];
    }
}

// ---------------- host launcher --------------------------------------------
extern "C" void kernel_launch(void* const* d_in, const int* in_sizes, int n_in,
                              void* d_out, int out_size) {
    const float* hidden   = (const float*)d_in[0];
    const void*  mask     = d_in[1];
    const float* fallback = (const float*)d_in[2];
    const float* gw1      = (const float*)d_in[3];
    const float* gb1      = (const float*)d_in[4];
    const float* gw2      = (const float*)d_in[5];
    const float* gb2      = (const float*)d_in[6];
    const float* wq       = (const float*)d_in[7];
    const float* wk       = (const float*)d_in[8];
    const float* wv       = (const float*)d_in[9];
    const float* rq       = (const float*)d_in[10];
    const float* rk       = (const float*)d_in[11];
    const float* rv       = (const float*)d_in[12];
    const float* ro       = (const float*)d_in[13];
    const float* g_ws_w   = (const float*)d_in[14];
    const float* b_ws_w   = (const float*)d_in[15];
    const float* g_out_w  = (const float*)d_in[16];
    const float* b_out_w  = (const float*)d_in[17];
    float* out = (float*)d_out;

    float *ctx, *h1, *ws, *qw, *kw, *vw, *wsu, *qr, *kr, *vr, *bc0, *bc;
    cudaGetSymbolAddress((void**)&ctx, buf_ctx);
    cudaGetSymbolAddress((void**)&h1,  buf_h1);
    cudaGetSymbolAddress((void**)&ws,  buf_ws);
    cudaGetSymbolAddress((void**)&qw,  buf_qw);
    cudaGetSymbolAddress((void**)&kw,  buf_kw);
    cudaGetSymbolAddress((void**)&vw,  buf_vw);
    cudaGetSymbolAddress((void**)&wsu, buf_wsu);
    cudaGetSymbolAddress((void**)&qr,  buf_qr);
    cudaGetSymbolAddress((void**)&kr,  buf_kr);
    cudaGetSymbolAddress((void**)&vr,  buf_vr);
    cudaGetSymbolAddress((void**)&bc0, buf_bc0);
    cudaGetSymbolAddress((void**)&bc,  buf_bc);

    ctx_kernel<<<NB, ND>>>(hidden, mask);

    sgemm_tc<<<dim3(1024/128, 8192/128), 256>>>(ctx, gw1, h1, 8192, 1024, 512,
                                                gb1, nullptr, 1);
    sgemm_tc<<<dim3(2048/128, 8192/128), 256>>>(h1, gw2, ws, 8192, 2048, 1024,
                                                gb2, fallback, 0);
    sgemm_tc<<<dim3(512/128, 32768/128), 256>>>(ws, wq, qw, 32768, 512, 512,
                                                nullptr, nullptr, 0);
    sgemm_tc<<<dim3(512/128, 131072/128), 256>>>(hidden, wk, kw, 131072, 512, 512,
                                                 nullptr, nullptr, 0);
    sgemm_tc<<<dim3(512/128, 131072/128), 256>>>(hidden, wv, vw, 131072, 512, 512,
                                                 nullptr, nullptr, 0);
    attn1_kernel<<<NB, 256>>>(g_ws_w, b_ws_w);

    sgemm_tc<<<dim3(512/128, 131072/128), 256>>>(hidden, rq, qr, 131072, 512, 512,
                                                 nullptr, nullptr, 0);
    sgemm_tc<<<dim3(512/128, 32768/128), 256>>>(wsu, rk, kr, 32768, 512, 512,
                                                nullptr, nullptr, 0);
    sgemm_tc<<<dim3(512/128, 32768/128), 256>>>(wsu, rv, vr, 32768, 512, 512,
                                                nullptr, nullptr, 0);
    attn2_kernel<<<NB, 256>>>();

    sgemm_tc<<<dim3(512/128, 131072/128), 256>>>(bc0, ro, bc, 131072, 512, 512,
                                                 nullptr, nullptr, 0);
    lnout_kernel<<<(NB * NK) / 8, 256>>>(hidden, g_out_w, b_out_w, out);
}

// round 4
// speedup vs baseline: 1.2655x; 1.2655x over previous
#include <cuda_runtime.h>

#define NB 8192
#define NK 16
#define ND 512
#define NS 4

// ---------------- scratch (device globals: allocation-free) ----------------
__device__ float buf_ctx [(size_t)NB * ND];
__device__ float buf_mkf [(size_t)NB * NK];
__device__ float buf_h1  [(size_t)NB * 2 * ND];
__device__ float buf_ws  [(size_t)NB * NS * ND];
__device__ float buf_qw  [(size_t)NB * NS * ND];
__device__ float buf_wsu [(size_t)NB * NS * ND];
__device__ float buf_bc0 [(size_t)NB * NK * ND];
__device__ float buf_bc  [(size_t)NB * NK * ND];
__device__ float buf_kvq [(size_t)NB * NK * 1536];   // [Kw|Vw|Qr] row stride 1536
__device__ float buf_krv [(size_t)NB * NS * 1024];   // [Kr|Vr]    row stride 1024
__device__ float buf_wp1 [512 * 1536];               // [wk|wv|rq]
__device__ float buf_wp2 [512 * 1024];               // [rk|rv]

__device__ __forceinline__ float warp_sum(float v) {
    #pragma unroll
    for (int o = 16; o > 0; o >>= 1) v += __shfl_xor_sync(0xffffffffu, v, o);
    return v;
}

__device__ __forceinline__ float f2tf32(float f) {
    unsigned r;
    asm("cvt.rna.tf32.f32 %0, %1;" : "=r"(r) : "f"(f));
    return __uint_as_float(r);
}

__device__ __forceinline__ void mma_tf32(float c[4], const unsigned a[4], const unsigned b[2]) {
    asm volatile(
        "mma.sync.aligned.m16n8k8.row.col.f32.tf32.tf32.f32 "
        "{%0,%1,%2,%3}, {%4,%5,%6,%7}, {%8,%9}, {%0,%1,%2,%3};"
        : "+f"(c[0]), "+f"(c[1]), "+f"(c[2]), "+f"(c[3])
        : "r"(a[0]), "r"(a[1]), "r"(a[2]), "r"(a[3]), "r"(b[0]), "r"(b[1]));
}

__device__ __forceinline__ void ldsm_x4(unsigned r[4], unsigned saddr) {
    asm volatile("ldmatrix.sync.aligned.m8n8.x4.shared.b16 {%0,%1,%2,%3}, [%4];"
        : "=r"(r[0]), "=r"(r[1]), "=r"(r[2]), "=r"(r[3]) : "r"(saddr));
}

// ---------------- weight packing -------------------------------------------
__global__ void pack1_kernel(const float* __restrict__ wk, const float* __restrict__ wv,
                             const float* __restrict__ rq) {
    int idx = blockIdx.x * 256 + threadIdx.x;       // f4 index, 196608 total
    int r = idx / 384, c = (idx % 384) * 4;
    const float* src = (c < 512) ? wk : (c < 1024) ? wv : rq;
    int off = c & 511;
    *(float4*)&buf_wp1[r * 1536 + c] = *(const float4*)&src[r * 512 + off];
}
__global__ void pack2_kernel(const float* __restrict__ rk, const float* __restrict__ rv) {
    int idx = blockIdx.x * 256 + threadIdx.x;       // f4 index, 131072 total
    int r = idx / 256, c = (idx % 256) * 4;
    const float* src = (c < 512) ? rk : rv;
    int off = c & 511;
    *(float4*)&buf_wp2[r * 1024 + c] = *(const float4*)&src[r * 512 + off];
}

// ---------------- masked context pooling (float4) ---------------------------
__global__ void ctx_kernel(const float* __restrict__ hidden, const void* mask_raw) {
    const int b = blockIdx.x;
    const int tid = threadIdx.x;              // 128 threads, one f4-column each
    __shared__ float sm[NK];
    __shared__ int smode;
    if (tid == 0) {
        const unsigned char* p = (const unsigned char*)mask_raw;
        int mode = 0;
        for (int i = 0; i < 512; ++i) {
            unsigned char v = p[i];
            if (!v) continue;
            if (v != 1u) { mode = 2; break; }
            if (i & 3)   { mode = 1; break; }
        }
        smode = mode;
    }
    __syncthreads();
    const int mode = smode;
    if (tid < NK) {
        int idx = b * NK + tid;
        float m;
        if (mode == 1)      m = ((const unsigned char*)mask_raw)[idx] ? 1.f : 0.f;
        else if (mode == 0) m = ((const int*)mask_raw)[idx] ? 1.f : 0.f;
        else                m = ((const float*)mask_raw)[idx];
        sm[tid] = m;
        buf_mkf[idx] = m;
    }
    __syncthreads();
    float n = 0.f;
    #pragma unroll
    for (int k = 0; k < NK; ++k) n += sm[k];
    const float inv = 1.f / fmaxf(n, 1.f);
    float4 acc = make_float4(0.f, 0.f, 0.f, 0.f);
    const float4* h4 = (const float4*)(hidden + (size_t)b * NK * ND);
    #pragma unroll
    for (int k = 0; k < NK; ++k) {
        float m = sm[k];
        float4 v = h4[k * 128 + tid];
        acc.x += m * v.x; acc.y += m * v.y; acc.z += m * v.z; acc.w += m * v.w;
    }
    ((float4*)(buf_ctx + (size_t)b * ND))[tid] =
        make_float4(acc.x * inv, acc.y * inv, acc.z * inv, acc.w * inv);
}

// ---------------- TF32 tensor-core SGEMM (ldmatrix A path) ------------------
// 128x128 CTA tile, BK=16, 8 warps (2x4), 64x32 warp tile, double-buffered.
// As row-major stride 20 (80B rows -> conflict-free LDSM); Bs [16][136].
#define ASTR 20
#define BSTR 136
__global__ void __launch_bounds__(256, 2)
sgemm_tc(const float* __restrict__ A, const float* __restrict__ B,
         float* __restrict__ C, int M, int N, int K,
         const float* __restrict__ bias1, const float* __restrict__ bias2,
         int do_gelu) {
    __shared__ __align__(16) float As[2][128 * ASTR];
    __shared__ __align__(16) float Bs[2][16 * BSTR];

    const int bm = blockIdx.y * 128;
    const int bn = blockIdx.x * 128;
    const int tid  = threadIdx.x;
    const int warp = tid >> 5;
    const int lane = tid & 31;
    const int gid  = lane >> 2;
    const int tig  = lane & 3;
    const int wm   = (warp >> 2) * 64;
    const int wn   = (warp & 3) * 32;

    // ldmatrix per-lane source row/col inside a 16x8 fragment block
    const int q   = lane >> 3;               // quadrant 0..3
    const int rr  = lane & 7;
    const int lrow = (q & 1) * 8 + rr;        // +0 / +8
    const int lcol = (q >> 1) * 4;            // +0 / +4
    unsigned asBase[2];
    asBase[0] = (unsigned)__cvta_generic_to_shared(&As[0][(wm + lrow) * ASTR + lcol]);
    asBase[1] = (unsigned)__cvta_generic_to_shared(&As[1][(wm + lrow) * ASTR + lcol]);

    float acc[4][4][4];
    #pragma unroll
    for (int i = 0; i < 4; ++i)
        #pragma unroll
        for (int j = 0; j < 4; ++j)
            #pragma unroll
            for (int r = 0; r < 4; ++r) acc[i][j][r] = 0.f;

    const int nk = K >> 4;

    auto fill = [&](int st, int k0) {
        #pragma unroll
        for (int it = 0; it < 2; ++it) {
            const int idx = tid + 256 * it;
            const int row = idx >> 2, kq = (idx & 3) * 4;
            float4 av = *(const float4*)(A + (size_t)(bm + row) * K + k0 + kq);
            *(float4*)&As[st][row * ASTR + kq] =
                make_float4(f2tf32(av.x), f2tf32(av.y), f2tf32(av.z), f2tf32(av.w));
            const int kr = idx >> 5, n4 = (idx & 31) * 4;
            float4 bv = *(const float4*)(B + (size_t)(k0 + kr) * N + bn + n4);
            *(float4*)&Bs[st][kr * BSTR + n4] =
                make_float4(f2tf32(bv.x), f2tf32(bv.y), f2tf32(bv.z), f2tf32(bv.w));
        }
    };

    fill(0, 0);
    __syncthreads();

    for (int kt = 0; kt < nk; ++kt) {
        const int st = kt & 1;
        if (kt + 1 < nk) fill(st ^ 1, (kt + 1) << 4);

        #pragma unroll
        for (int kb = 0; kb < 2; ++kb) {
            unsigned afr[4][4], bfr[4][2];
            #pragma unroll
            for (int i = 0; i < 4; ++i)
                ldsm_x4(afr[i], asBase[st] + (unsigned)((i * 16 * ASTR + kb * 8) * 4));
            #pragma unroll
            for (int j = 0; j < 4; ++j) {
                const int col = wn + j * 8 + gid;
                bfr[j][0] = __float_as_uint(Bs[st][(kb * 8 + tig)     * BSTR + col]);
                bfr[j][1] = __float_as_uint(Bs[st][(kb * 8 + tig + 4) * BSTR + col]);
            }
            #pragma unroll
            for (int i = 0; i < 4; ++i)
                #pragma unroll
                for (int j = 0; j < 4; ++j)
                    mma_tf32(acc[i][j], afr[i], bfr[j]);
        }
        __syncthreads();
    }

    #pragma unroll
    for (int i = 0; i < 4; ++i) {
        #pragma unroll
        for (int j = 0; j < 4; ++j) {
            #pragma unroll
            for (int half = 0; half < 2; ++half) {
                const int row = bm + wm + i * 16 + gid + half * 8;
                const int col = bn + wn + j * 8 + tig * 2;
                float v0 = acc[i][j][half * 2 + 0];
                float v1 = acc[i][j][half * 2 + 1];
                if (bias1) { v0 += bias1[col]; v1 += bias1[col + 1]; }
                if (bias2) { v0 += bias2[col]; v1 += bias2[col + 1]; }
                if (do_gelu) {
                    v0 = 0.5f * v0 * (1.f + erff(v0 * 0.70710678118654752f));
                    v1 = 0.5f * v1 * (1.f + erff(v1 * 0.70710678118654752f));
                }
                *(float2*)(C + (size_t)row * N + col) = make_float2(v0, v1);
            }
        }
    }
}

// ---------------- attention #1 (ws queries hidden) + LN ---------------------
__global__ void __launch_bounds__(256) attn1_kernel(const float* __restrict__ gamma,
                                                    const float* __restrict__ beta) {
    __shared__ __align__(16) float sq[NS * ND];     // q, reused for y
    __shared__ __align__(16) float sv[NK * ND];
    __shared__ float slog[64], swt[64];
    const int b = blockIdx.x;
    const int tid = threadIdx.x;
    const int warp = tid >> 5;
    const int lane = tid & 31;

    {
        const float4* qg = (const float4*)(buf_qw + (size_t)b * NS * ND);
        ((float4*)sq)[tid] = qg[tid];
        ((float4*)sq)[tid + 256] = qg[tid + 256];
        #pragma unroll
        for (int i = 0; i < 8; ++i) {
            const int idx = tid + 256 * i;
            const int k = idx >> 7, c4 = idx & 127;
            ((float4*)sv)[idx] =
                *(const float4*)(buf_kvq + ((size_t)(b * NK + k)) * 1536 + 512 + 4 * c4);
        }
    }
    __syncthreads();

    // logits: warp w -> pairs p = 8w..8w+7 (s = p>>4, k = p&15)
    {
        const int p0 = warp * 8;
        float acc[8];
        #pragma unroll
        for (int u = 0; u < 8; ++u) acc[u] = 0.f;
        #pragma unroll
        for (int j = 0; j < 4; ++j) {
            const int c = lane + 32 * j;
            #pragma unroll
            for (int u = 0; u < 8; ++u) {
                const int p = p0 + u, s = p >> 4, k = p & 15;
                float4 q4 = ((const float4*)sq)[s * 128 + c];
                float4 k4 = *(const float4*)(buf_kvq + ((size_t)(b * NK + k)) * 1536 + 4 * c);
                acc[u] += q4.x * k4.x + q4.y * k4.y + q4.z * k4.z + q4.w * k4.w;
            }
        }
        #pragma unroll
        for (int u = 0; u < 8; ++u) acc[u] = warp_sum(acc[u]);
        if (lane == 0) {
            #pragma unroll
            for (int u = 0; u < 8; ++u) slog[p0 + u] = acc[u];
        }
    }
    __syncthreads();

    if (tid < NS) {
        const int s = tid;
        const float scale = 0.04419417382415922f;
        float lg[NK];
        float mx = -1e30f;
        int any = 0;
        #pragma unroll
        for (int k = 0; k < NK; ++k) {
            float m = buf_mkf[b * NK + k];
            float l = (m > 0.5f) ? slog[s * NK + k] * scale : -1e30f;
            if (m > 0.5f) any = 1;
            lg[k] = l;
            mx = fmaxf(mx, l);
        }
        float den = 0.f;
        #pragma unroll
        for (int k = 0; k < NK; ++k) { lg[k] = expf(lg[k] - mx); den += lg[k]; }
        const float inv = any ? (1.f / den) : 0.f;
        #pragma unroll
        for (int k = 0; k < NK; ++k) swt[s * NK + k] = lg[k] * inv;
    }
    __syncthreads();

    {
        const float4* wsb = (const float4*)(buf_ws + (size_t)b * NS * ND);
        #pragma unroll
        for (int i = 0; i < 2; ++i) {
            const int idx = tid + 256 * i;
            const int s = idx >> 7, c4 = idx & 127;
            float4 o = make_float4(0.f, 0.f, 0.f, 0.f);
            #pragma unroll
            for (int k = 0; k < NK; ++k) {
                const float w = swt[s * NK + k];
                float4 v4 = ((const float4*)sv)[k * 128 + c4];
                o.x += w * v4.x; o.y += w * v4.y; o.z += w * v4.z; o.w += w * v4.w;
            }
            float4 w4 = wsb[idx];
            ((float4*)sq)[idx] = make_float4(o.x + w4.x, o.y + w4.y, o.z + w4.z, o.w + w4.w);
        }
    }
    __syncthreads();

    if (warp < NS) {
        const int s = warp;
        float4 y[4];
        #pragma unroll
        for (int j = 0; j < 4; ++j) y[j] = ((const float4*)sq)[s * 128 + lane + 32 * j];
        float sum = 0.f;
        #pragma unroll
        for (int j = 0; j < 4; ++j) sum += y[j].x + y[j].y + y[j].z + y[j].w;
        const float mu = warp_sum(sum) * (1.f / ND);
        float sqs = 0.f;
        #pragma unroll
        for (int j = 0; j < 4; ++j) {
            float cx = y[j].x - mu, cy = y[j].y - mu, cz = y[j].z - mu, cw = y[j].w - mu;
            sqs += cx * cx + cy * cy + cz * cz + cw * cw;
        }
        const float var = warp_sum(sqs) * (1.f / ND);
        const float rstd = rsqrtf(var + 1e-5f);
        #pragma unroll
        for (int j = 0; j < 4; ++j) {
            const int d4 = lane + 32 * j;
            float4 g4 = ((const float4*)gamma)[d4];
            float4 b4 = ((const float4*)beta)[d4];
            float4 o;
            o.x = (y[j].x - mu) * rstd * g4.x + b4.x;
            o.y = (y[j].y - mu) * rstd * g4.y + b4.y;
            o.z = (y[j].z - mu) * rstd * g4.z + b4.z;
            o.w = (y[j].w - mu) * rstd * g4.w + b4.w;
            ((float4*)(buf_wsu + ((size_t)b * NS + s) * ND))[d4] = o;
        }
    }
}

// ---------------- attention #2 (hidden queries ws_upd) ----------------------
__global__ void __launch_bounds__(256) attn2_kernel() {
    __shared__ __align__(16) float skr[NS * ND];
    __shared__ __align__(16) float svr[NS * ND];
    __shared__ float slog[64], swt2[64];
    const int b = blockIdx.x;
    const int tid = threadIdx.x;
    const int warp = tid >> 5;
    const int lane = tid & 31;

    #pragma unroll
    for (int i = 0; i < 2; ++i) {
        const int idx = tid + 256 * i;
        const int s = idx >> 7, c4 = idx & 127;
        const float* base = buf_krv + (size_t)(b * NS + s) * 1024;
        ((float4*)skr)[idx] = *(const float4*)(base + 4 * c4);
        ((float4*)svr)[idx] = *(const float4*)(base + 512 + 4 * c4);
    }
    __syncthreads();

    // logits: warp w owns tokens 2w, 2w+1
    {
        float acc[2][4];
        #pragma unroll
        for (int i = 0; i < 2; ++i)
            #pragma unroll
            for (int s = 0; s < 4; ++s) acc[i][s] = 0.f;
        #pragma unroll
        for (int j = 0; j < 4; ++j) {
            const int c = lane + 32 * j;
            float4 q0 = *(const float4*)(buf_kvq + ((size_t)(b * NK + 2 * warp))     * 1536 + 1024 + 4 * c);
            float4 q1 = *(const float4*)(buf_kvq + ((size_t)(b * NK + 2 * warp + 1)) * 1536 + 1024 + 4 * c);
            #pragma unroll
            for (int s = 0; s < 4; ++s) {
                float4 k4 = ((const float4*)skr)[s * 128 + c];
                acc[0][s] += q0.x * k4.x + q0.y * k4.y + q0.z * k4.z + q0.w * k4.w;
                acc[1][s] += q1.x * k4.x + q1.y * k4.y + q1.z * k4.z + q1.w * k4.w;
            }
        }
        #pragma unroll
        for (int i = 0; i < 2; ++i)
            #pragma unroll
            for (int s = 0; s < 4; ++s) acc[i][s] = warp_sum(acc[i][s]);
        if (lane == 0) {
            #pragma unroll
            for (int i = 0; i < 2; ++i)
                #pragma unroll
                for (int s = 0; s < 4; ++s) slog[(2 * warp + i) * NS + s] = acc[i][s];
        }
    }
    __syncthreads();

    if (tid < NK) {
        const int k = tid;
        const float scale = 0.04419417382415922f;
        float lg[NS];
        float mx = -1e30f;
        #pragma unroll
        for (int s = 0; s < NS; ++s) { lg[s] = slog[k * NS + s] * scale; mx = fmaxf(mx, lg[s]); }
        float den = 0.f;
        #pragma unroll
        for (int s = 0; s < NS; ++s) { lg[s] = expf(lg[s] - mx); den += lg[s]; }
        const float inv = 1.f / den;
        #pragma unroll
        for (int s = 0; s < NS; ++s) swt2[k * NS + s] = lg[s] * inv;
    }
    __syncthreads();

    #pragma unroll
    for (int i = 0; i < 8; ++i) {
        const int idx = tid + 256 * i;
        const int k = idx >> 7, c4 = idx & 127;
        const float w0 = swt2[k * NS + 0], w1 = swt2[k * NS + 1];
        const float w2 = swt2[k * NS + 2], w3 = swt2[k * NS + 3];
        float4 v0 = ((const float4*)svr)[c4];
        float4 v1 = ((const float4*)svr)[128 + c4];
        float4 v2 = ((const float4*)svr)[256 + c4];
        float4 v3 = ((const float4*)svr)[384 + c4];
        float4 o;
        o.x = w0 * v0.x + w1 * v1.x + w2 * v2.x + w3 * v3.x;
        o.y = w0 * v0.y + w1 * v1.y + w2 * v2.y + w3 * v3.y;
        o.z = w0 * v0.z + w1 * v1.z + w2 * v2.z + w3 * v3.z;
        o.w = w0 * v0.w + w1 * v1.w + w2 * v2.w + w3 * v3.w;
        *(float4*)(buf_bc0 + (size_t)(b * NK + k) * ND + 4 * c4) = o;
    }
}

// ---------------- final residual + layernorm (float4) -----------------------
__global__ void __launch_bounds__(256) lnout_kernel(const float* __restrict__ hidden,
                                                    const float* __restrict__ gamma,
                                                    const float* __restrict__ beta,
                                                    float* __restrict__ out) {
    const int row = blockIdx.x * 8 + (threadIdx.x >> 5);
    const int lane = threadIdx.x & 31;
    const float4* h4 = (const float4*)(hidden + (size_t)row * ND);
    const float4* b4p = (const float4*)(buf_bc + (size_t)row * ND);
    float4 y[4];
    #pragma unroll
    for (int j = 0; j < 4; ++j) {
        float4 a = h4[lane + 32 * j], c = b4p[lane + 32 * j];
        y[j] = make_float4(a.x + c.x, a.y + c.y, a.z + c.z, a.w + c.w);
    }
    float sum = 0.f;
    #pragma unroll
    for (int j = 0; j < 4; ++j) sum += y[j].x + y[j].y + y[j].z + y[j].w;
    const float mu = warp_sum(sum) * (1.f / ND);
    float sqs = 0.f;
    #pragma unroll
    for (int j = 0; j < 4; ++j) {
        float cx = y[j].x - mu, cy = y[j].y - mu, cz = y[j].z - mu, cw = y[j].w - mu;
        sqs += cx * cx + cy * cy + cz * cz + cw * cw;
    }
    const float var = warp_sum(sqs) * (1.f / ND);
    const float rstd = rsqrtf(var + 1e-5f);
    #pragma unroll
    for (int j = 0; j < 4; ++j) {
        const int d4 = lane + 32 * j;
        float4 g4 = ((const float4*)gamma)[d4];
        float4 bb = ((const float4*)beta)[d4];
        float4 o;
        o.x = (y[j].x - mu) * rstd * g4.x + bb.x;
        o.y = (y[j].y - mu) * rstd * g4.y + bb.y;
        o.z = (y[j].z - mu) * rstd * g4.z + bb.z;
        o.w = (y[j].w - mu) * rstd * g4.w + bb.w;
        ((float4*)(out + (size_t)row * ND))[d4] = o;
    }
}

// ---------------- host launcher --------------------------------------------
extern "C" void kernel_launch(void* const* d_in, const int* in_sizes, int n_in,
                              void* d_out, int out_size) {
    const float* hidden   = (const float*)d_in[0];
    const void*  mask     = d_in[1];
    const float* fallback = (const float*)d_in[2];
    const float* gw1      = (const float*)d_in[3];
    const float* gb1      = (const float*)d_in[4];
    const float* gw2      = (const float*)d_in[5];
    const float* gb2      = (const float*)d_in[6];
    const float* wq       = (const float*)d_in[7];
    const float* wk       = (const float*)d_in[8];
    const float* wv       = (const float*)d_in[9];
    const float* rq       = (const float*)d_in[10];
    const float* rk       = (const float*)d_in[11];
    const float* rv       = (const float*)d_in[12];
    const float* ro       = (const float*)d_in[13];
    const float* g_ws_w   = (const float*)d_in[14];
    const float* b_ws_w   = (const float*)d_in[15];
    const float* g_out_w  = (const float*)d_in[16];
    const float* b_out_w  = (const float*)d_in[17];
    float* out = (float*)d_out;

    float *ctx, *h1, *ws, *qw, *wsu, *bc0, *bc, *kvq, *krv, *wp1, *wp2;
    cudaGetSymbolAddress((void**)&ctx, buf_ctx);
    cudaGetSymbolAddress((void**)&h1,  buf_h1);
    cudaGetSymbolAddress((void**)&ws,  buf_ws);
    cudaGetSymbolAddress((void**)&qw,  buf_qw);
    cudaGetSymbolAddress((void**)&wsu, buf_wsu);
    cudaGetSymbolAddress((void**)&bc0, buf_bc0);
    cudaGetSymbolAddress((void**)&bc,  buf_bc);
    cudaGetSymbolAddress((void**)&kvq, buf_kvq);
    cudaGetSymbolAddress((void**)&krv, buf_krv);
    cudaGetSymbolAddress((void**)&wp1, buf_wp1);
    cudaGetSymbolAddress((void**)&wp2, buf_wp2);

    // 1-2) pack weights
    pack1_kernel<<<768, 256>>>(wk, wv, rq);
    pack2_kernel<<<512, 256>>>(rk, rv);
    // 3) context pooling
    ctx_kernel<<<NB, 128>>>(hidden, mask);
    // 4) h1 = gelu(ctx @ gw1 + gb1)
    sgemm_tc<<<dim3(8, 64), 256>>>(ctx, gw1, h1, 8192, 1024, 512, gb1, nullptr, 1);
    // 5) ws = h1 @ gw2 + gb2 + fallback
    sgemm_tc<<<dim3(16, 64), 256>>>(h1, gw2, ws, 8192, 2048, 1024, gb2, fallback, 0);
    // 6) [Kw|Vw|Qr] = hidden @ wp1   (the big one; ncu captures this launch)
    sgemm_tc<<<dim3(12, 1024), 256>>>(hidden, wp1, kvq, 131072, 1536, 512,
                                      nullptr, nullptr, 0);
    // 7) Qw = ws @ wq
    sgemm_tc<<<dim3(4, 256), 256>>>(ws, wq, qw, 32768, 512, 512, nullptr, nullptr, 0);
    // 8) attention #1 + layernorm -> ws_upd
    attn1_kernel<<<NB, 256>>>(g_ws_w, b_ws_w);
    // 9) [Kr|Vr] = ws_upd @ wp2
    sgemm_tc<<<dim3(8, 256), 256>>>(wsu, wp2, krv, 32768, 1024, 512, nullptr, nullptr, 0);
    // 10) attention #2 -> bc0
    attn2_kernel<<<NB, 256>>>();
    // 11) bc = bc0 @ ro
    sgemm_tc<<<dim3(4, 1024), 256>>>(bc0, ro, bc, 131072, 512, 512, nullptr, nullptr, 0);
    // 12) out = layernorm(hidden + bc)
    lnout_kernel<<<(NB * NK) / 8, 256>>>(hidden, g_out_w, b_out_w, out);
}

// round 5
// speedup vs baseline: 1.8041x; 1.4257x over previous
#include <cuda_runtime.h>

#define NB 8192
#define NK 16
#define ND 512
#define NS 4

// ---------------- scratch (device globals: allocation-free) ----------------
__device__ float buf_ctx [(size_t)NB * ND];
__device__ float buf_mkf [(size_t)NB * NK];
__device__ float buf_h1  [(size_t)NB * 2 * ND];
__device__ float buf_ws  [(size_t)NB * NS * ND];
__device__ float buf_qw  [(size_t)NB * NS * ND];
__device__ float buf_wsu [(size_t)NB * NS * ND];
__device__ float buf_bc0 [(size_t)NB * NK * ND];
__device__ float buf_bc  [(size_t)NB * NK * ND];
__device__ float buf_kvq [(size_t)NB * NK * 1536];   // [Kw|Vw|Qr] row stride 1536
__device__ float buf_krv [(size_t)NB * NS * 1024];   // [Kr|Vr]    row stride 1024
__device__ float buf_wp1 [512 * 1536];               // [wk|wv|rq]
__device__ float buf_wp2 [512 * 1024];               // [rk|rv]

__device__ __forceinline__ float warp_sum(float v) {
    #pragma unroll
    for (int o = 16; o > 0; o >>= 1) v += __shfl_xor_sync(0xffffffffu, v, o);
    return v;
}

__device__ __forceinline__ void mma_tf32(float c[4], const unsigned a[4], const unsigned b[2]) {
    asm volatile(
        "mma.sync.aligned.m16n8k8.row.col.f32.tf32.tf32.f32 "
        "{%0,%1,%2,%3}, {%4,%5,%6,%7}, {%8,%9}, {%0,%1,%2,%3};"
        : "+f"(c[0]), "+f"(c[1]), "+f"(c[2]), "+f"(c[3])
        : "r"(a[0]), "r"(a[1]), "r"(a[2]), "r"(a[3]), "r"(b[0]), "r"(b[1]));
}

__device__ __forceinline__ void ldsm_x4(unsigned r[4], unsigned saddr) {
    asm volatile("ldmatrix.sync.aligned.m8n8.x4.shared.b16 {%0,%1,%2,%3}, [%4];"
        : "=r"(r[0]), "=r"(r[1]), "=r"(r[2]), "=r"(r[3]) : "r"(saddr));
}

__device__ __forceinline__ void cp_async16(unsigned saddr, const void* gaddr) {
    asm volatile("cp.async.cg.shared.global [%0], [%1], 16;" :: "r"(saddr), "l"(gaddr));
}
__device__ __forceinline__ void cp_commit() {
    asm volatile("cp.async.commit_group;");
}
template <int N>
__device__ __forceinline__ void cp_wait() {
    asm volatile("cp.async.wait_group %0;" :: "n"(N));
}

// ---------------- weight packing -------------------------------------------
__global__ void pack1_kernel(const float* __restrict__ wk, const float* __restrict__ wv,
                             const float* __restrict__ rq) {
    int idx = blockIdx.x * 256 + threadIdx.x;       // f4 index, 196608 total
    int r = idx / 384, c = (idx % 384) * 4;
    const float* src = (c < 512) ? wk : (c < 1024) ? wv : rq;
    int off = c & 511;
    *(float4*)&buf_wp1[r * 1536 + c] = *(const float4*)&src[r * 512 + off];
}
__global__ void pack2_kernel(const float* __restrict__ rk, const float* __restrict__ rv) {
    int idx = blockIdx.x * 256 + threadIdx.x;       // f4 index, 131072 total
    int r = idx / 256, c = (idx % 256) * 4;
    const float* src = (c < 512) ? rk : rv;
    int off = c & 511;
    *(float4*)&buf_wp2[r * 1024 + c] = *(const float4*)&src[r * 512 + off];
}

// ---------------- masked context pooling (float4) ---------------------------
__global__ void ctx_kernel(const float* __restrict__ hidden, const void* mask_raw) {
    const int b = blockIdx.x;
    const int tid = threadIdx.x;              // 128 threads, one f4-column each
    __shared__ float sm[NK];
    __shared__ int smode;
    if (tid == 0) {
        const unsigned char* p = (const unsigned char*)mask_raw;
        int mode = 0;
        for (int i = 0; i < 512; ++i) {
            unsigned char v = p[i];
            if (!v) continue;
            if (v != 1u) { mode = 2; break; }
            if (i & 3)   { mode = 1; break; }
        }
        smode = mode;
    }
    __syncthreads();
    const int mode = smode;
    if (tid < NK) {
        int idx = b * NK + tid;
        float m;
        if (mode == 1)      m = ((const unsigned char*)mask_raw)[idx] ? 1.f : 0.f;
        else if (mode == 0) m = ((const int*)mask_raw)[idx] ? 1.f : 0.f;
        else                m = ((const float*)mask_raw)[idx];
        sm[tid] = m;
        buf_mkf[idx] = m;
    }
    __syncthreads();
    float n = 0.f;
    #pragma unroll
    for (int k = 0; k < NK; ++k) n += sm[k];
    const float inv = 1.f / fmaxf(n, 1.f);
    float4 acc = make_float4(0.f, 0.f, 0.f, 0.f);
    const float4* h4 = (const float4*)(hidden + (size_t)b * NK * ND);
    #pragma unroll
    for (int k = 0; k < NK; ++k) {
        float m = sm[k];
        float4 v = h4[k * 128 + tid];
        acc.x += m * v.x; acc.y += m * v.y; acc.z += m * v.z; acc.w += m * v.w;
    }
    ((float4*)(buf_ctx + (size_t)b * ND))[tid] =
        make_float4(acc.x * inv, acc.y * inv, acc.z * inv, acc.w * inv);
}

// ---------------- TF32 tensor-core SGEMM, cp.async 4-stage pipeline ---------
// 128x128 CTA tile, BK=16, 8 warps (2x4), 64x32 warp tile.
// As row-major stride 20 (conflict-free LDSM rows); Bs [16][136].
// Inputs fed raw to mma.tf32 (HW truncation) -> no cvt in the fill path.
#define ASTR 20
#define BSTR 136
#define NSTG 4
#define ASZ (128 * ASTR * 4)
#define BSZ (16 * BSTR * 4)

__global__ void __launch_bounds__(256, 2)
sgemm_tc(const float* __restrict__ A, const float* __restrict__ B,
         float* __restrict__ C, int M, int N, int K,
         const float* __restrict__ bias1, const float* __restrict__ bias2,
         int do_gelu) {
    __shared__ __align__(16) float As[NSTG][128 * ASTR];
    __shared__ __align__(16) float Bs[NSTG][16 * BSTR];

    const int bm = blockIdx.y * 128;
    const int bn = blockIdx.x * 128;
    const int tid  = threadIdx.x;
    const int warp = tid >> 5;
    const int lane = tid & 31;
    const int gid  = lane >> 2;
    const int tig  = lane & 3;
    const int wm   = (warp >> 2) * 64;
    const int wn   = (warp & 3) * 32;

    // ldmatrix per-lane source row/col inside a 16x8 fragment block
    const int q    = lane >> 3;
    const int rr   = lane & 7;
    const int lrow = (q & 1) * 8 + rr;
    const int lcol = (q >> 1) * 4;

    const unsigned aBase = (unsigned)__cvta_generic_to_shared(&As[0][0]);
    const unsigned bBase = (unsigned)__cvta_generic_to_shared(&Bs[0][0]);
    const unsigned aFrag = aBase + (unsigned)(((wm + lrow) * ASTR + lcol) * 4);

    // fill addressing (per thread)
    const int frow = tid >> 2;            // 0..63
    const int fkq  = (tid & 3) * 4;       // 0,4,8,12
    const int fkr  = tid >> 5;            // 0..7
    const int fn4  = (tid & 31) * 4;      // 0..124
    const float* Ag = A + (size_t)(bm + frow) * K + fkq;
    const float* Bg = B + (size_t)fkr * N + bn + fn4;
    const unsigned asOff = (unsigned)((frow * ASTR + fkq) * 4);
    const unsigned bsOff = (unsigned)((fkr * BSTR + fn4) * 4);

    float acc[4][4][4];
    #pragma unroll
    for (int i = 0; i < 4; ++i)
        #pragma unroll
        for (int j = 0; j < 4; ++j)
            #pragma unroll
            for (int r = 0; r < 4; ++r) acc[i][j][r] = 0.f;

    const int nk = K >> 4;

    auto fill = [&](int st, int k0) {
        const unsigned as0 = aBase + st * ASZ + asOff;
        cp_async16(as0,                     Ag + k0);
        cp_async16(as0 + 64 * ASTR * 4,     Ag + (size_t)64 * K + k0);
        const unsigned bs0 = bBase + st * BSZ + bsOff;
        cp_async16(bs0,                     Bg + (size_t)k0 * N);
        cp_async16(bs0 + 8 * BSTR * 4,      Bg + (size_t)(k0 + 8) * N);
    };

    // prologue: fill stages 0..NSTG-2
    #pragma unroll
    for (int s = 0; s < NSTG - 1; ++s) {
        fill(s, s * 16);
        cp_commit();
    }
    cp_wait<NSTG - 2>();
    __syncthreads();

    for (int kt = 0; kt < nk; ++kt) {
        const int st = kt & (NSTG - 1);

        #pragma unroll
        for (int kb = 0; kb < 2; ++kb) {
            unsigned afr[4][4], bfr[4][2];
            #pragma unroll
            for (int i = 0; i < 4; ++i)
                ldsm_x4(afr[i], aFrag + (unsigned)(st * ASZ + (i * 16 * ASTR + kb * 8) * 4));
            #pragma unroll
            for (int j = 0; j < 4; ++j) {
                const int col = wn + j * 8 + gid;
                bfr[j][0] = __float_as_uint(Bs[st][(kb * 8 + tig)     * BSTR + col]);
                bfr[j][1] = __float_as_uint(Bs[st][(kb * 8 + tig + 4) * BSTR + col]);
            }
            #pragma unroll
            for (int i = 0; i < 4; ++i)
                #pragma unroll
                for (int j = 0; j < 4; ++j)
                    mma_tf32(acc[i][j], afr[i], bfr[j]);
        }

        if (kt + NSTG - 1 < nk)
            fill((kt + NSTG - 1) & (NSTG - 1), (kt + NSTG - 1) << 4);
        cp_commit();
        cp_wait<NSTG - 2>();
        __syncthreads();
    }

    #pragma unroll
    for (int i = 0; i < 4; ++i) {
        #pragma unroll
        for (int j = 0; j < 4; ++j) {
            #pragma unroll
            for (int half = 0; half < 2; ++half) {
                const int row = bm + wm + i * 16 + gid + half * 8;
                const int col = bn + wn + j * 8 + tig * 2;
                float v0 = acc[i][j][half * 2 + 0];
                float v1 = acc[i][j][half * 2 + 1];
                if (bias1) { v0 += bias1[col]; v1 += bias1[col + 1]; }
                if (bias2) { v0 += bias2[col]; v1 += bias2[col + 1]; }
                if (do_gelu) {
                    v0 = 0.5f * v0 * (1.f + erff(v0 * 0.70710678118654752f));
                    v1 = 0.5f * v1 * (1.f + erff(v1 * 0.70710678118654752f));
                }
                *(float2*)(C + (size_t)row * N + col) = make_float2(v0, v1);
            }
        }
    }
}

// ---------------- attention #1 (ws queries hidden) + LN ---------------------
__global__ void __launch_bounds__(256) attn1_kernel(const float* __restrict__ gamma,
                                                    const float* __restrict__ beta) {
    __shared__ __align__(16) float sq[NS * ND];     // q, reused for y
    __shared__ __align__(16) float sv[NK * ND];
    __shared__ float slog[64], swt[64];
    const int b = blockIdx.x;
    const int tid = threadIdx.x;
    const int warp = tid >> 5;
    const int lane = tid & 31;

    {
        const float4* qg = (const float4*)(buf_qw + (size_t)b * NS * ND);
        ((float4*)sq)[tid] = qg[tid];
        ((float4*)sq)[tid + 256] = qg[tid + 256];
        #pragma unroll
        for (int i = 0; i < 8; ++i) {
            const int idx = tid + 256 * i;
            const int k = idx >> 7, c4 = idx & 127;
            ((float4*)sv)[idx] =
                *(const float4*)(buf_kvq + ((size_t)(b * NK + k)) * 1536 + 512 + 4 * c4);
        }
    }
    __syncthreads();

    {
        const int p0 = warp * 8;
        float acc[8];
        #pragma unroll
        for (int u = 0; u < 8; ++u) acc[u] = 0.f;
        #pragma unroll
        for (int j = 0; j < 4; ++j) {
            const int c = lane + 32 * j;
            #pragma unroll
            for (int u = 0; u < 8; ++u) {
                const int p = p0 + u, s = p >> 4, k = p & 15;
                float4 q4 = ((const float4*)sq)[s * 128 + c];
                float4 k4 = *(const float4*)(buf_kvq + ((size_t)(b * NK + k)) * 1536 + 4 * c);
                acc[u] += q4.x * k4.x + q4.y * k4.y + q4.z * k4.z + q4.w * k4.w;
            }
        }
        #pragma unroll
        for (int u = 0; u < 8; ++u) acc[u] = warp_sum(acc[u]);
        if (lane == 0) {
            #pragma unroll
            for (int u = 0; u < 8; ++u) slog[p0 + u] = acc[u];
        }
    }
    __syncthreads();

    if (tid < NS) {
        const int s = tid;
        const float scale = 0.04419417382415922f;
        float lg[NK];
        float mx = -1e30f;
        int any = 0;
        #pragma unroll
        for (int k = 0; k < NK; ++k) {
            float m = buf_mkf[b * NK + k];
            float l = (m > 0.5f) ? slog[s * NK + k] * scale : -1e30f;
            if (m > 0.5f) any = 1;
            lg[k] = l;
            mx = fmaxf(mx, l);
        }
        float den = 0.f;
        #pragma unroll
        for (int k = 0; k < NK; ++k) { lg[k] = expf(lg[k] - mx); den += lg[k]; }
        const float inv = any ? (1.f / den) : 0.f;
        #pragma unroll
        for (int k = 0; k < NK; ++k) swt[s * NK + k] = lg[k] * inv;
    }
    __syncthreads();

    {
        const float4* wsb = (const float4*)(buf_ws + (size_t)b * NS * ND);
        #pragma unroll
        for (int i = 0; i < 2; ++i) {
            const int idx = tid + 256 * i;
            const int s = idx >> 7, c4 = idx & 127;
            float4 o = make_float4(0.f, 0.f, 0.f, 0.f);
            #pragma unroll
            for (int k = 0; k < NK; ++k) {
                const float w = swt[s * NK + k];
                float4 v4 = ((const float4*)sv)[k * 128 + c4];
                o.x += w * v4.x; o.y += w * v4.y; o.z += w * v4.z; o.w += w * v4.w;
            }
            float4 w4 = wsb[idx];
            ((float4*)sq)[idx] = make_float4(o.x + w4.x, o.y + w4.y, o.z + w4.z, o.w + w4.w);
        }
    }
    __syncthreads();

    if (warp < NS) {
        const int s = warp;
        float4 y[4];
        #pragma unroll
        for (int j = 0; j < 4; ++j) y[j] = ((const float4*)sq)[s * 128 + lane + 32 * j];
        float sum = 0.f;
        #pragma unroll
        for (int j = 0; j < 4; ++j) sum += y[j].x + y[j].y + y[j].z + y[j].w;
        const float mu = warp_sum(sum) * (1.f / ND);
        float sqs = 0.f;
        #pragma unroll
        for (int j = 0; j < 4; ++j) {
            float cx = y[j].x - mu, cy = y[j].y - mu, cz = y[j].z - mu, cw = y[j].w - mu;
            sqs += cx * cx + cy * cy + cz * cz + cw * cw;
        }
        const float var = warp_sum(sqs) * (1.f / ND);
        const float rstd = rsqrtf(var + 1e-5f);
        #pragma unroll
        for (int j = 0; j < 4; ++j) {
            const int d4 = lane + 32 * j;
            float4 g4 = ((const float4*)gamma)[d4];
            float4 b4 = ((const float4*)beta)[d4];
            float4 o;
            o.x = (y[j].x - mu) * rstd * g4.x + b4.x;
            o.y = (y[j].y - mu) * rstd * g4.y + b4.y;
            o.z = (y[j].z - mu) * rstd * g4.z + b4.z;
            o.w = (y[j].w - mu) * rstd * g4.w + b4.w;
            ((float4*)(buf_wsu + ((size_t)b * NS + s) * ND))[d4] = o;
        }
    }
}

// ---------------- attention #2 (hidden queries ws_upd) ----------------------
__global__ void __launch_bounds__(256) attn2_kernel() {
    __shared__ __align__(16) float skr[NS * ND];
    __shared__ __align__(16) float svr[NS * ND];
    __shared__ float slog[64], swt2[64];
    const int b = blockIdx.x;
    const int tid = threadIdx.x;
    const int warp = tid >> 5;
    const int lane = tid & 31;

    #pragma unroll
    for (int i = 0; i < 2; ++i) {
        const int idx = tid + 256 * i;
        const int s = idx >> 7, c4 = idx & 127;
        const float* base = buf_krv + (size_t)(b * NS + s) * 1024;
        ((float4*)skr)[idx] = *(const float4*)(base + 4 * c4);
        ((float4*)svr)[idx] = *(const float4*)(base + 512 + 4 * c4);
    }
    __syncthreads();

    {
        float acc[2][4];
        #pragma unroll
        for (int i = 0; i < 2; ++i)
            #pragma unroll
            for (int s = 0; s < 4; ++s) acc[i][s] = 0.f;
        #pragma unroll
        for (int j = 0; j < 4; ++j) {
            const int c = lane + 32 * j;
            float4 q0 = *(const float4*)(buf_kvq + ((size_t)(b * NK + 2 * warp))     * 1536 + 1024 + 4 * c);
            float4 q1 = *(const float4*)(buf_kvq + ((size_t)(b * NK + 2 * warp + 1)) * 1536 + 1024 + 4 * c);
            #pragma unroll
            for (int s = 0; s < 4; ++s) {
                float4 k4 = ((const float4*)skr)[s * 128 + c];
                acc[0][s] += q0.x * k4.x + q0.y * k4.y + q0.z * k4.z + q0.w * k4.w;
                acc[1][s] += q1.x * k4.x + q1.y * k4.y + q1.z * k4.z + q1.w * k4.w;
            }
        }
        #pragma unroll
        for (int i = 0; i < 2; ++i)
            #pragma unroll
            for (int s = 0; s < 4; ++s) acc[i][s] = warp_sum(acc[i][s]);
        if (lane == 0) {
            #pragma unroll
            for (int i = 0; i < 2; ++i)
                #pragma unroll
                for (int s = 0; s < 4; ++s) slog[(2 * warp + i) * NS + s] = acc[i][s];
        }
    }
    __syncthreads();

    if (tid < NK) {
        const int k = tid;
        const float scale = 0.04419417382415922f;
        float lg[NS];
        float mx = -1e30f;
        #pragma unroll
        for (int s = 0; s < NS; ++s) { lg[s] = slog[k * NS + s] * scale; mx = fmaxf(mx, lg[s]); }
        float den = 0.f;
        #pragma unroll
        for (int s = 0; s < NS; ++s) { lg[s] = expf(lg[s] - mx); den += lg[s]; }
        const float inv = 1.f / den;
        #pragma unroll
        for (int s = 0; s < NS; ++s) swt2[k * NS + s] = lg[s] * inv;
    }
    __syncthreads();

    #pragma unroll
    for (int i = 0; i < 8; ++i) {
        const int idx = tid + 256 * i;
        const int k = idx >> 7, c4 = idx & 127;
        const float w0 = swt2[k * NS + 0], w1 = swt2[k * NS + 1];
        const float w2 = swt2[k * NS + 2], w3 = swt2[k * NS + 3];
        float4 v0 = ((const float4*)svr)[c4];
        float4 v1 = ((const float4*)svr)[128 + c4];
        float4 v2 = ((const float4*)svr)[256 + c4];
        float4 v3 = ((const float4*)svr)[384 + c4];
        float4 o;
        o.x = w0 * v0.x + w1 * v1.x + w2 * v2.x + w3 * v3.x;
        o.y = w0 * v0.y + w1 * v1.y + w2 * v2.y + w3 * v3.y;
        o.z = w0 * v0.z + w1 * v1.z + w2 * v2.z + w3 * v3.z;
        o.w = w0 * v0.w + w1 * v1.w + w2 * v2.w + w3 * v3.w;
        *(float4*)(buf_bc0 + (size_t)(b * NK + k) * ND + 4 * c4) = o;
    }
}

// ---------------- final residual + layernorm (float4) -----------------------
__global__ void __launch_bounds__(256) lnout_kernel(const float* __restrict__ hidden,
                                                    const float* __restrict__ gamma,
                                                    const float* __restrict__ beta,
                                                    float* __restrict__ out) {
    const int row = blockIdx.x * 8 + (threadIdx.x >> 5);
    const int lane = threadIdx.x & 31;
    const float4* h4 = (const float4*)(hidden + (size_t)row * ND);
    const float4* b4p = (const float4*)(buf_bc + (size_t)row * ND);
    float4 y[4];
    #pragma unroll
    for (int j = 0; j < 4; ++j) {
        float4 a = h4[lane + 32 * j], c = b4p[lane + 32 * j];
        y[j] = make_float4(a.x + c.x, a.y + c.y, a.z + c.z, a.w + c.w);
    }
    float sum = 0.f;
    #pragma unroll
    for (int j = 0; j < 4; ++j) sum += y[j].x + y[j].y + y[j].z + y[j].w;
    const float mu = warp_sum(sum) * (1.f / ND);
    float sqs = 0.f;
    #pragma unroll
    for (int j = 0; j < 4; ++j) {
        float cx = y[j].x - mu, cy = y[j].y - mu, cz = y[j].z - mu, cw = y[j].w - mu;
        sqs += cx * cx + cy * cy + cz * cz + cw * cw;
    }
    const float var = warp_sum(sqs) * (1.f / ND);
    const float rstd = rsqrtf(var + 1e-5f);
    #pragma unroll
    for (int j = 0; j < 4; ++j) {
        const int d4 = lane + 32 * j;
        float4 g4 = ((const float4*)gamma)[d4];
        float4 bb = ((const float4*)beta)[d4];
        float4 o;
        o.x = (y[j].x - mu) * rstd * g4.x + bb.x;
        o.y = (y[j].y - mu) * rstd * g4.y + bb.y;
        o.z = (y[j].z - mu) * rstd * g4.z + bb.z;
        o.w = (y[j].w - mu) * rstd * g4.w + bb.w;
        ((float4*)(out + (size_t)row * ND))[d4] = o;
    }
}

// ---------------- host launcher --------------------------------------------
extern "C" void kernel_launch(void* const* d_in, const int* in_sizes, int n_in,
                              void* d_out, int out_size) {
    const float* hidden   = (const float*)d_in[0];
    const void*  mask     = d_in[1];
    const float* fallback = (const float*)d_in[2];
    const float* gw1      = (const float*)d_in[3];
    const float* gb1      = (const float*)d_in[4];
    const float* gw2      = (const float*)d_in[5];
    const float* gb2      = (const float*)d_in[6];
    const float* wq       = (const float*)d_in[7];
    const float* wk       = (const float*)d_in[8];
    const float* wv       = (const float*)d_in[9];
    const float* rq       = (const float*)d_in[10];
    const float* rk       = (const float*)d_in[11];
    const float* rv       = (const float*)d_in[12];
    const float* ro       = (const float*)d_in[13];
    const float* g_ws_w   = (const float*)d_in[14];
    const float* b_ws_w   = (const float*)d_in[15];
    const float* g_out_w  = (const float*)d_in[16];
    const float* b_out_w  = (const float*)d_in[17];
    float* out = (float*)d_out;

    float *ctx, *h1, *ws, *qw, *wsu, *bc0, *bc, *kvq, *krv, *wp1, *wp2;
    cudaGetSymbolAddress((void**)&ctx, buf_ctx);
    cudaGetSymbolAddress((void**)&h1,  buf_h1);
    cudaGetSymbolAddress((void**)&ws,  buf_ws);
    cudaGetSymbolAddress((void**)&qw,  buf_qw);
    cudaGetSymbolAddress((void**)&wsu, buf_wsu);
    cudaGetSymbolAddress((void**)&bc0, buf_bc0);
    cudaGetSymbolAddress((void**)&bc,  buf_bc);
    cudaGetSymbolAddress((void**)&kvq, buf_kvq);
    cudaGetSymbolAddress((void**)&krv, buf_krv);
    cudaGetSymbolAddress((void**)&wp1, buf_wp1);
    cudaGetSymbolAddress((void**)&wp2, buf_wp2);

    // 1-2) pack weights
    pack1_kernel<<<768, 256>>>(wk, wv, rq);
    pack2_kernel<<<512, 256>>>(rk, rv);
    // 3) context pooling
    ctx_kernel<<<NB, 128>>>(hidden, mask);
    // 4) h1 = gelu(ctx @ gw1 + gb1)
    sgemm_tc<<<dim3(8, 64), 256>>>(ctx, gw1, h1, 8192, 1024, 512, gb1, nullptr, 1);
    // 5) ws = h1 @ gw2 + gb2 + fallback
    sgemm_tc<<<dim3(16, 64), 256>>>(h1, gw2, ws, 8192, 2048, 1024, gb2, fallback, 0);
    // 6) [Kw|Vw|Qr] = hidden @ wp1
    sgemm_tc<<<dim3(12, 1024), 256>>>(hidden, wp1, kvq, 131072, 1536, 512,
                                      nullptr, nullptr, 0);
    // 7) Qw = ws @ wq
    sgemm_tc<<<dim3(4, 256), 256>>>(ws, wq, qw, 32768, 512, 512, nullptr, nullptr, 0);
    // 8) attention #1 + layernorm -> ws_upd
    attn1_kernel<<<NB, 256>>>(g_ws_w, b_ws_w);
    // 9) [Kr|Vr] = ws_upd @ wp2
    sgemm_tc<<<dim3(8, 256), 256>>>(wsu, wp2, krv, 32768, 1024, 512, nullptr, nullptr, 0);
    // 10) attention #2 -> bc0
    attn2_kernel<<<NB, 256>>>();
    // 11) bc = bc0 @ ro
    sgemm_tc<<<dim3(4, 1024), 256>>>(bc0, ro, bc, 131072, 512, 512, nullptr, nullptr, 0);
    // 12) out = layernorm(hidden + bc)
    lnout_kernel<<<(NB * NK) / 8, 256>>>(hidden, g_out_w, b_out_w, out);
}